// round 1
// baseline (speedup 1.0000x reference)
#include <cuda_runtime.h>

#define N 1024

// Order-preserving float -> uint32 mapping (exact, bijective, monotone).
__device__ __forceinline__ unsigned fkey(float f) {
    unsigned k = __float_as_uint(f);
    return (k & 0x80000000u) ? ~k : (k | 0x80000000u);
}
__device__ __forceinline__ float funkey(unsigned k) {
    unsigned b = (k & 0x80000000u) ? (k & 0x7fffffffu) : ~k;
    return __uint_as_float(b);
}

// Exact Jonker-Volgenant LAP (same algorithm as the reference's _hungarian),
// one persistent block, one thread per column. Cost C(i,j) = ||a_i - b_j||
// recomputed on the fly (a in shared, b in registers).
__global__ __launch_bounds__(1024, 1)
void emd_jv_kernel(const float* __restrict__ gt,
                   const float* __restrict__ gen,
                   float* __restrict__ out) {
    __shared__ float s_ax[N], s_ay[N], s_az[N];
    __shared__ float s_u[N];              // row potentials
    __shared__ int   s_p[N];              // p[j] = row matched to column j (-1 free)
    __shared__ unsigned short s_way[N];   // predecessor column on alternating path
    __shared__ unsigned s_wmin[32];
    __shared__ unsigned s_min;
    __shared__ unsigned s_j1;
    __shared__ int s_i0;                  // row to relax from (p[j0]); -1 => augment
    __shared__ float s_sum[32];

    const int j    = threadIdx.x;
    const int lane = j & 31;
    const int wid  = j >> 5;

    // Load points: a (rows) to shared, b (columns) to registers.
    s_ax[j] = gt[3 * j + 0];
    s_ay[j] = gt[3 * j + 1];
    s_az[j] = gt[3 * j + 2];
    const float bx = gen[3 * j + 0];
    const float by = gen[3 * j + 1];
    const float bz = gen[3 * j + 2];
    s_u[j] = 0.0f;
    s_p[j] = -1;
    float v = 0.0f;                       // column potential (thread-private)
    __syncthreads();

    for (int i = 0; i < N; ++i) {
        float minv = 3.0e38f;
        bool  used = false;
        int   j0   = N;                   // virtual column
        if (j == 0) s_i0 = i;             // p[virtual] = i
        __syncthreads();

        while (true) {
            // ---- relax all free columns from row i0 = p[j0] ----
            const int   i0  = s_i0;
            const float ui0 = s_u[i0];
            const float ax = s_ax[i0], ay = s_ay[i0], az = s_az[i0];
            unsigned key;
            if (!used) {
                const float dx = ax - bx, dy = ay - by, dz = az - bz;
                const float c  = sqrtf(fmaf(dx, dx, fmaf(dy, dy, dz * dz)));
                const float cur = c - ui0 - v;
                if (cur < minv) { minv = cur; s_way[j] = (unsigned short)j0; }
                key = fkey(minv);
            } else {
                key = 0xffffffffu;
            }

            // ---- argmin over free columns ----
            const unsigned wm = __reduce_min_sync(0xffffffffu, key);
            if (lane == 0) s_wmin[wid] = wm;
            __syncthreads();
            if (j < 32) {
                const unsigned m = __reduce_min_sync(0xffffffffu, s_wmin[j]);
                if (j == 0) { s_min = m; s_j1 = 0xffffffffu; }
            }
            __syncthreads();
            const unsigned gm = s_min;
            if (key == gm) atomicMin(&s_j1, (unsigned)j);
            __syncthreads();

            const float delta = funkey(gm);
            const int   j1    = (int)s_j1;

            // ---- dual/potential updates (matches reference ordering) ----
            if (used) {
                v -= delta;
                s_u[s_p[j]] += delta;     // distinct rows per used column: no conflict
            } else {
                minv -= delta;
            }
            if (j == 0) s_u[i] += delta;  // virtual column's row = i

            // ---- settle j1; fetch its matched row (or -1 = free) ----
            if (j == j1) { s_i0 = s_p[j]; used = true; }
            __syncthreads();

            if (s_i0 < 0) {
                // j1 is free: augment alternating path back to virtual column.
                if (j == 0) {
                    int jj = j1;
                    while (true) {
                        const int jw = s_way[jj];
                        if (jw == N) { s_p[jj] = i; break; }
                        s_p[jj] = s_p[jw];
                        jj = jw;
                    }
                }
                break;
            }
            j0 = j1;
        }
        __syncthreads();   // augment writes to s_p visible before next row
    }

    // ---- mean of matched distances ----
    const int pi = s_p[j];
    const float dx = s_ax[pi] - bx, dy = s_ay[pi] - by, dz = s_az[pi] - bz;
    float c = sqrtf(fmaf(dx, dx, fmaf(dy, dy, dz * dz)));
    #pragma unroll
    for (int o = 16; o; o >>= 1) c += __shfl_down_sync(0xffffffffu, c, o);
    if (lane == 0) s_sum[wid] = c;
    __syncthreads();
    if (j == 0) {
        float s = 0.0f;
        #pragma unroll
        for (int w = 0; w < 32; ++w) s += s_sum[w];
        out[0] = s * (1.0f / 1024.0f);
    }
}

extern "C" void kernel_launch(void* const* d_in, const int* in_sizes, int n_in,
                              void* d_out, int out_size) {
    const float* gt  = (const float*)d_in[0];   // (1,1024,3) fp32
    const float* gen = (const float*)d_in[1];   // (1,1024,3) fp32
    (void)in_sizes; (void)n_in; (void)out_size;
    emd_jv_kernel<<<1, 1024>>>(gt, gen, (float*)d_out);
}